// round 1
// baseline (speedup 1.0000x reference)
#include <cuda_runtime.h>

// Problem dims (fixed by the reference setup_inputs)
#define B_  256
#define F_  300
#define JC_ 1600
#define NC_ 60
#define J4_ (JC_ / 4)   // 400 float4 per frame

// Scratch for pooled features [B, JC] (device global: allocation-free)
__device__ float g_pooled[B_ * JC_];

// ---------------------------------------------------------------------------
// Kernel 1: masked prefix-mean pooling over frames.
// grid = (B_), block = (J4_ = 400). Each thread owns one float4 column.
// Coalesced: a block reads 6400 contiguous bytes per frame.
// ---------------------------------------------------------------------------
__global__ __launch_bounds__(J4_) void pool_kernel(
    const float* __restrict__ x,       // [B, F, JC]
    const int*   __restrict__ lengths) // [B]
{
    const int b  = blockIdx.x;
    const int j4 = threadIdx.x;        // 0..399

    const int len = lengths[b];
    const float4* __restrict__ xb =
        reinterpret_cast<const float4*>(x + (size_t)b * F_ * JC_);

    float4 acc;
    if (len <= 1) {
        // reference edge case: <=1 valid frames -> take frame 0 directly
        acc = xb[j4];
    } else {
        float ax = 0.f, ay = 0.f, az = 0.f, aw = 0.f;
        int f = 0;
        // unrolled by 4 for memory-level parallelism
        for (; f + 4 <= len; f += 4) {
            float4 v0 = xb[(size_t)(f + 0) * J4_ + j4];
            float4 v1 = xb[(size_t)(f + 1) * J4_ + j4];
            float4 v2 = xb[(size_t)(f + 2) * J4_ + j4];
            float4 v3 = xb[(size_t)(f + 3) * J4_ + j4];
            ax += v0.x + v1.x + v2.x + v3.x;
            ay += v0.y + v1.y + v2.y + v3.y;
            az += v0.z + v1.z + v2.z + v3.z;
            aw += v0.w + v1.w + v2.w + v3.w;
        }
        for (; f < len; f++) {
            float4 v = xb[(size_t)f * J4_ + j4];
            ax += v.x; ay += v.y; az += v.z; aw += v.w;
        }
        const float inv = 1.0f / (float)len;
        acc.x = ax * inv; acc.y = ay * inv; acc.z = az * inv; acc.w = aw * inv;
    }
    reinterpret_cast<float4*>(g_pooled)[(size_t)b * J4_ + j4] = acc;
}

// ---------------------------------------------------------------------------
// Kernel 2: out[b, n] = pooled[b, :] . W[:, n] + bias[n]
// grid = (B_), block = 64 (60 active for the dot product).
// W (384 KB) is L2-resident across blocks.
// ---------------------------------------------------------------------------
__global__ __launch_bounds__(64) void fc_kernel(
    const float* __restrict__ W,     // [JC, NC] row-major
    const float* __restrict__ bias,  // [NC]
    float*       __restrict__ out)   // [B, NC]
{
    __shared__ float sp[JC_];
    const int b = blockIdx.x;

    // stage pooled row in shared
    const float4* prow = reinterpret_cast<const float4*>(g_pooled + (size_t)b * JC_);
    for (int i = threadIdx.x; i < J4_; i += blockDim.x) {
        float4 v = prow[i];
        sp[i * 4 + 0] = v.x; sp[i * 4 + 1] = v.y;
        sp[i * 4 + 2] = v.z; sp[i * 4 + 3] = v.w;
    }
    __syncthreads();

    const int n = threadIdx.x;
    if (n < NC_) {
        float acc = bias[n];
#pragma unroll 8
        for (int j = 0; j < JC_; j++) {
            acc += sp[j] * W[(size_t)j * NC_ + n];
        }
        out[(size_t)b * NC_ + n] = acc;
    }
}

extern "C" void kernel_launch(void* const* d_in, const int* in_sizes, int n_in,
                              void* d_out, int out_size)
{
    const float* x       = (const float*)d_in[0];
    const int*   lengths = (const int*)  d_in[1];
    const float* W       = (const float*)d_in[2];
    const float* bias    = (const float*)d_in[3];
    float*       out     = (float*)d_out;

    pool_kernel<<<B_, J4_>>>(x, lengths);
    fc_kernel<<<B_, 64>>>(W, bias, out);
}

// round 2
// speedup vs baseline: 2.1547x; 2.1547x over previous
#include <cuda_runtime.h>

// Problem dims (fixed by the reference setup_inputs)
#define B_    256
#define F_    300
#define JC_   1600
#define NC_   60
#define J4_   (JC_ / 4)   // 400 float4 per frame
#define CHUNK 30          // frames per pooling block
#define NCH   (F_ / CHUNK) // 10 chunks

// Partial sums [B, NCH, J4] as float4 (16.4 MB device scratch; allocation-free)
__device__ float4 g_part[(size_t)B_ * NCH * J4_];

// ---------------------------------------------------------------------------
// Kernel 1: partial frame sums. grid = (B, NCH), block = 400.
// Block (b,c) sums frames [c*30, min((c+1)*30, len)). Bounded work per block
// (<= 30 frames = 192 KB) -> good load balance across 2560 blocks.
// ---------------------------------------------------------------------------
__global__ __launch_bounds__(J4_) void pool_part_kernel(
    const float* __restrict__ x,       // [B, F, JC]
    const int*   __restrict__ lengths) // [B]
{
    const int b  = blockIdx.x;
    const int c  = blockIdx.y;
    const int j4 = threadIdx.x;

    const int len = lengths[b];
    const int f0  = c * CHUNK;
    const int f1  = min(f0 + CHUNK, len);

    const float4* __restrict__ xb =
        reinterpret_cast<const float4*>(x + (size_t)b * F_ * JC_);

    float ax = 0.f, ay = 0.f, az = 0.f, aw = 0.f;
    int f = f0;
    for (; f + 4 <= f1; f += 4) {
        float4 v0 = xb[(size_t)(f + 0) * J4_ + j4];
        float4 v1 = xb[(size_t)(f + 1) * J4_ + j4];
        float4 v2 = xb[(size_t)(f + 2) * J4_ + j4];
        float4 v3 = xb[(size_t)(f + 3) * J4_ + j4];
        ax += v0.x + v1.x + v2.x + v3.x;
        ay += v0.y + v1.y + v2.y + v3.y;
        az += v0.z + v1.z + v2.z + v3.z;
        aw += v0.w + v1.w + v2.w + v3.w;
    }
    for (; f < f1; f++) {
        float4 v = xb[(size_t)f * J4_ + j4];
        ax += v.x; ay += v.y; az += v.z; aw += v.w;
    }
    g_part[((size_t)b * NCH + c) * J4_ + j4] = make_float4(ax, ay, az, aw);
}

// ---------------------------------------------------------------------------
// Kernel 2: fused reduce + mean + edge case + FC.
// grid = (B), block = 512.
// Phase A (t<400): sum the 10 chunk partials (L2-hit), divide by len,
//                  or take frame 0 directly when len<=1; stage row in shared.
// Phase B (t<480): 8 j-groups x 60 outputs, each thread a 200-length dot.
// Phase C (t<60):  tree-combine the 8 partials + bias -> out.
// ---------------------------------------------------------------------------
__global__ __launch_bounds__(512) void reduce_fc_kernel(
    const float* __restrict__ x,       // [B, F, JC] (for len<=1 edge case)
    const int*   __restrict__ lengths, // [B]
    const float* __restrict__ W,       // [JC, NC] row-major
    const float* __restrict__ bias,    // [NC]
    float*       __restrict__ out)     // [B, NC]
{
    __shared__ float sp[JC_];
    __shared__ float red[8 * NC_];

    const int b = blockIdx.x;
    const int t = threadIdx.x;
    const int len = lengths[b];

    if (t < J4_) {
        float4 s;
        if (len <= 1) {
            // reference edge case: <=1 valid frames -> frame 0 directly
            s = reinterpret_cast<const float4*>(x + (size_t)b * F_ * JC_)[t];
        } else {
            float ax = 0.f, ay = 0.f, az = 0.f, aw = 0.f;
#pragma unroll
            for (int c = 0; c < NCH; c++) {
                float4 v = g_part[((size_t)b * NCH + c) * J4_ + t];
                ax += v.x; ay += v.y; az += v.z; aw += v.w;
            }
            const float inv = 1.0f / (float)len;
            s = make_float4(ax * inv, ay * inv, az * inv, aw * inv);
        }
        reinterpret_cast<float4*>(sp)[t] = s;
    }
    __syncthreads();

    if (t < 8 * NC_) {
        const int g = t / NC_;          // j-group 0..7
        const int n = t - g * NC_;      // output 0..59 (consecutive -> coalesced W)
        const float* __restrict__ Wn = W + n;
        const int j0 = g * (JC_ / 8);   // 200 j per group
        float acc = 0.f;
#pragma unroll 4
        for (int j = j0; j < j0 + JC_ / 8; j++) {
            acc += sp[j] * Wn[(size_t)j * NC_];
        }
        red[t] = acc;
    }
    __syncthreads();

    if (t < NC_) {
        float acc = bias[t];
#pragma unroll
        for (int g = 0; g < 8; g++) acc += red[g * NC_ + t];
        out[(size_t)b * NC_ + t] = acc;
    }
}

extern "C" void kernel_launch(void* const* d_in, const int* in_sizes, int n_in,
                              void* d_out, int out_size)
{
    const float* x       = (const float*)d_in[0];
    const int*   lengths = (const int*)  d_in[1];
    const float* W       = (const float*)d_in[2];
    const float* bias    = (const float*)d_in[3];
    float*       out     = (float*)d_out;

    dim3 grid_pool(B_, NCH);
    pool_part_kernel<<<grid_pool, J4_>>>(x, lengths);
    reduce_fc_kernel<<<B_, 512>>>(x, lengths, W, bias, out);
}